// round 14
// baseline (speedup 1.0000x reference)
#include <cuda_runtime.h>
#include <cstdint>

typedef unsigned long long ull;

#define TPB   256
#define NB    8
#define R_    16
#define D_    1024

// ---- packed f32x2 helpers ----
__device__ __forceinline__ ull ffma2(ull a, ull b, ull c) {
    ull d;
    asm("fma.rn.f32x2 %0, %1, %2, %3;" : "=l"(d) : "l"(a), "l"(b), "l"(c));
    return d;
}
__device__ __forceinline__ ull fmul2(ull a, ull b) {
    ull d;
    asm("mul.rn.f32x2 %0, %1, %2;" : "=l"(d) : "l"(a), "l"(b));
    return d;
}
__device__ __forceinline__ ull fadd2(ull a, ull b) {
    ull d;
    asm("add.rn.f32x2 %0, %1, %2;" : "=l"(d) : "l"(a), "l"(b));
    return d;
}
__device__ __forceinline__ float lo_(ull v) { return __int_as_float((int)(unsigned)(v & 0xffffffffull)); }
__device__ __forceinline__ float hi_(ull v) { return __int_as_float((int)(unsigned)(v >> 32)); }
__device__ __forceinline__ ull   dup_(float v) {
    ull d;
    asm("mov.b64 %0, {%1, %1};" : "=l"(d) : "r"(__float_as_uint(v)));
    return d;
}
__device__ __forceinline__ ull pack2_(float l, float h) {
    ull d;
    asm("mov.b64 %0, {%1, %2};" : "=l"(d) : "r"(__float_as_uint(l)), "r"(__float_as_uint(h)));
    return d;
}
__device__ __forceinline__ ulonglong2 ldg128(const void* p) {
    ulonglong2 v;
    asm("ld.global.nc.v2.u64 {%0, %1}, [%2];" : "=l"(v.x), "=l"(v.y) : "l"(p));
    return v;
}
__device__ __forceinline__ void stcs128(void* p, ull a, ull b) {
    asm volatile("st.global.cs.v2.u64 [%0], {%1, %2};" :: "l"(p), "l"(a), "l"(b));
}
__device__ __forceinline__ unsigned sptr(const void* p) {
    return (unsigned)__cvta_generic_to_shared(p);
}
__device__ __forceinline__ void cpa16(unsigned dst, const void* src) {
    asm volatile("cp.async.cg.shared.global [%0], [%1], 16;" :: "r"(dst), "l"(src));
}

// ---- dynamic smem layout (per CTA, ~108.3 KB) ----
#define XS_OFF   0                       // ulonglong2 [3][NB][TPB]   98304 B
#define RED2_OFF 98304                   // ull   [NB][TPB/2]          8192 B
#define RED1_OFF 106496                  // float [NB][TPB/4]          2048 B
#define SB_OFF   108544                  // ull   [2][NB][R_]          2048 B
#define SIDX_OFF 110592                  // int   [4][NB]               128 B
#define SCX_OFF  110720                  // ull   [NB]                   64 B
#define SCY_OFF  110784                  // ull   [NB]                   64 B
#define SMEM_TOTAL 110848

__global__ __launch_bounds__(TPB, 2)
void rlora_kernel(const int*   __restrict__ indices,
                  const float* __restrict__ baseW,
                  const float* __restrict__ loraA,
                  const float* __restrict__ loraB,
                  float*       __restrict__ out,
                  int n_rows, int nbatch)
{
    extern __shared__ char smem_raw[];
    ulonglong2 (*xs)[NB][TPB]    = reinterpret_cast<ulonglong2(*)[NB][TPB]>(smem_raw + XS_OFF);
    ull   (*red2)[TPB / 2]       = reinterpret_cast<ull(*)[TPB / 2]>(smem_raw + RED2_OFF);
    float (*red1)[TPB / 4]       = reinterpret_cast<float(*)[TPB / 4]>(smem_raw + RED1_OFF);
    ull   (*sb)[NB][R_]          = reinterpret_cast<ull(*)[NB][R_]>(smem_raw + SB_OFF);
    int   (*sidx)[NB]            = reinterpret_cast<int(*)[NB]>(smem_raw + SIDX_OFF);
    ull*  scx                    = reinterpret_cast<ull*>(smem_raw + SCX_OFF);
    ull*  scy                    = reinterpret_cast<ull*>(smem_raw + SCY_OFF);

    const int tid  = threadIdx.x;
    const int wid  = tid >> 5;
    const int lane = tid & 31;
    const int d0   = tid * 4;            // this lane owns columns d0..d0+3

    // lora_A register-resident: a2[r] = A[r][d0..d0+3]  (64 regs)
    ulonglong2 a2[R_];
    #pragma unroll
    for (int r = 0; r < R_; ++r) a2[r] = ldg128(loraA + r * D_ + d0);

    const int S    = gridDim.x;
    const int b0   = blockIdx.x;
    const int kmax = (nbatch - b0 + S - 1) / S;

    // ---------------- prologue: batches 0 and 1 in flight ----------------
    #pragma unroll
    for (int m = 0; m < 2; ++m) {
        if (m < kmax) {
            #pragma unroll
            for (int row = 0; row < NB; ++row) {
                int g = (b0 + m * S) * NB + row;
                if (g < n_rows) {
                    int idx = __ldg(indices + g);
                    cpa16(sptr(&xs[m][row][tid]), baseW + (size_t)idx * D_ + d0);
                }
            }
        }
        asm volatile("cp.async.commit_group;");
    }
    // sidx slots 1..3 = indices of batches 1..3
    if (tid < NB) {
        #pragma unroll
        for (int m = 1; m < 4; ++m) {
            long long g = (long long)(b0 + m * S) * NB + tid;
            sidx[m][tid] = (m < kmax && g < n_rows) ? __ldg(indices + g) : -1;
        }
    }
    // sb slot 0 = batch 0 b-rows
    if (tid < NB * R_) {
        int row = tid >> 4, r = tid & 15;
        int g = b0 * NB + row;
        sb[0][row][r] = (g < n_rows)
            ? dup_(0.1f * __ldg(loraB + (size_t)__ldg(indices + g) * R_ + r)) : 0ull;
    }
    __syncthreads();

    int s_cur = 0;   // k % 3
    for (int k = 0; k < kmax; ++k) {
        const int s_pf = (s_cur + 2 >= 3) ? s_cur - 1 : s_cur + 2;   // (k+2) % 3

        // ---- step 1: cp.async batch k+2 into xs[(k+2)%3] ----
        if ((k + 2) < kmax) {
            #pragma unroll
            for (int row = 0; row < NB; ++row) {
                int idx = sidx[(k + 2) & 3][row];
                if (idx >= 0)
                    cpa16(sptr(&xs[s_pf][row][tid]), baseW + (size_t)idx * D_ + d0);
            }
        }
        asm volatile("cp.async.commit_group;");

        // ---- step 2: stage sidx(batch k+4) -> slot (k+4)&3 == k&3 ----
        if (tid < NB) {
            long long g = (long long)(b0 + (k + 4) * S) * NB + tid;
            sidx[k & 3][tid] = ((k + 4) < kmax && g < n_rows) ? __ldg(indices + g) : -1;
        }
        // ---- step 3: stage sb(batch k+1) -> sb[(k+1)&1] ----
        if (tid < NB * R_) {
            int row = tid >> 4, r = tid & 15;
            int idx = ((k + 1) < kmax) ? sidx[(k + 1) & 3][row] : -1;
            sb[(k + 1) & 1][row][r] = (idx >= 0)
                ? dup_(0.1f * __ldg(loraB + (size_t)idx * R_ + r)) : 0ull;
        }

        // ---- step 4: batch k landed (keep 2 newer groups pending) ----
        asm volatile("cp.async.wait_group 2;" ::: "memory");

        // ---- step 5: compute delta + prefolded partials ----
        const int p = k & 1;
        ulonglong2 xk[NB], dvk[NB];
        #pragma unroll
        for (int row = 0; row < NB; ++row) {
            ulonglong2 xv = xs[s_cur][row][tid];   // this thread's own copy
            xk[row] = xv;

            const ulonglong2* bp = reinterpret_cast<const ulonglong2*>(sb[p][row]);
            ulonglong2 b01 = bp[0];
            ull ax0 = fmul2(b01.x, a2[0].x), ay0 = fmul2(b01.x, a2[0].y);
            ull ax1 = fmul2(b01.y, a2[1].x), ay1 = fmul2(b01.y, a2[1].y);
            #pragma unroll
            for (int kk = 1; kk < R_ / 2; ++kk) {
                ulonglong2 b = bp[kk];
                ax0 = ffma2(b.x, a2[2 * kk].x,     ax0);
                ay0 = ffma2(b.x, a2[2 * kk].y,     ay0);
                ax1 = ffma2(b.y, a2[2 * kk + 1].x, ax1);
                ay1 = ffma2(b.y, a2[2 * kk + 1].y, ay1);
            }
            dvk[row].x = fadd2(ax0, ax1);
            dvk[row].y = fadd2(ay0, ay1);

            float x0 = lo_(xv.x), x1 = hi_(xv.x), x2c = lo_(xv.y), x3 = hi_(xv.y);
            float y0 = lo_(dvk[row].x), y1 = hi_(dvk[row].x);
            float y2c = lo_(dvk[row].y), y3 = hi_(dvk[row].y);

            float x2p = fmaf(x0, x0, fmaf(x1, x1, fmaf(x2c, x2c, x3 * x3)));
            float xyp = fmaf(x0, y0, fmaf(x1, y1, fmaf(x2c, y2c, x3 * y3)));
            float y2p = fmaf(y0, y0, fmaf(y1, y1, fmaf(y2c, y2c, y3 * y3)));

            x2p += __shfl_xor_sync(0xffffffffu, x2p, 16);
            xyp += __shfl_xor_sync(0xffffffffu, xyp, 16);
            y2p += __shfl_xor_sync(0xffffffffu, y2p, 16);
            y2p += __shfl_xor_sync(0xffffffffu, y2p, 8);
            if (lane < 16) red2[row][wid * 16 + lane] = pack2_(x2p, xyp);
            if (lane < 8)  red1[row][wid * 8 + lane]  = y2p;
        }
        __syncthreads();

        // ---- step 6: warp w reduces row w + epilogue ----
        {
            const ulonglong2* p2 = reinterpret_cast<const ulonglong2*>(red2[wid]);
            ulonglong2 v0 = p2[lane], v1 = p2[lane + 32];
            ull sp = fadd2(fadd2(v0.x, v0.y), fadd2(v1.x, v1.y));
            const float* r1 = red1[wid];
            float s2 = r1[lane] + r1[lane + 32];

            float a0 = lo_(sp), a1 = hi_(sp);
            #pragma unroll
            for (int off = 16; off > 0; off >>= 1) {
                a0 += __shfl_xor_sync(0xffffffffu, a0, off);
                a1 += __shfl_xor_sync(0xffffffffu, a1, off);
                s2 += __shfl_xor_sync(0xffffffffu, s2, off);
            }
            if (lane == 0) {
                const float MAXN = 1.0f - 1e-5f;
                const float EPSN = 1e-5f;
                float x2 = a0, xy = a1, y2 = s2;

                float nx = sqrtf(x2);
                float sx = (nx > MAXN) ? __fdividef(MAXN, fmaxf(nx, EPSN)) : 1.0f;
                float ny = sqrtf(y2);
                float sy = (ny > MAXN) ? __fdividef(MAXN, fmaxf(ny, EPSN)) : 1.0f;

                float X2 = sx * sx * x2;
                float Y2 = sy * sy * y2;
                float XY = sx * sy * xy;

                float A_  = 1.0f + 2.0f * XY + Y2;
                float B_  = 1.0f - X2;
                float den = fmaxf(1.0f + 2.0f * XY + X2 * Y2, 1e-15f);

                float n2 = (A_ * A_ * X2 + 2.0f * A_ * B_ * XY + B_ * B_ * Y2)
                           / (den * den);
                float no = sqrtf(fmaxf(n2, 0.0f));
                float sf = (no > MAXN) ? __fdividef(MAXN, fmaxf(no, EPSN)) : 1.0f;

                scx[wid] = dup_(__fdividef(sf * A_ * sx, den));
                scy[wid] = dup_(__fdividef(sf * B_ * sy, den));
            }
        }
        __syncthreads();

        // ---- step 7: store batch k ----
        const long long row0 = (long long)(b0 + k * S) * NB;
        #pragma unroll
        for (int row = 0; row < NB; ++row) {
            long long g = row0 + row;
            if (g < n_rows) {
                ull o0 = ffma2(scx[row], xk[row].x, fmul2(scy[row], dvk[row].x));
                ull o1 = ffma2(scx[row], xk[row].y, fmul2(scy[row], dvk[row].y));
                stcs128(out + (size_t)g * D_ + d0, o0, o1);
            }
        }

        s_cur = (s_cur + 1 >= 3) ? 0 : s_cur + 1;
    }
}

extern "C" void kernel_launch(void* const* d_in, const int* in_sizes, int n_in,
                              void* d_out, int out_size)
{
    const int*   indices = (const int*)  d_in[0];
    const float* baseW   = (const float*)d_in[1];
    const float* loraA   = (const float*)d_in[2];
    const float* loraB   = (const float*)d_in[3];
    float*       out     = (float*)d_out;

    int n_rows = in_sizes[0];                    // 32768
    int nbatch = (n_rows + NB - 1) / NB;         // 4096
    int grid   = nbatch < 2 * 148 ? nbatch : 2 * 148;   // 2 CTAs/SM

    cudaFuncSetAttribute(rlora_kernel,
                         cudaFuncAttributeMaxDynamicSharedMemorySize, SMEM_TOTAL);
    rlora_kernel<<<grid, TPB, SMEM_TOTAL>>>(indices, baseW, loraA, loraB, out,
                                            n_rows, nbatch);
}

// round 15
// speedup vs baseline: 1.1150x; 1.1150x over previous
#include <cuda_runtime.h>
#include <cstdint>

typedef unsigned long long ull;

#define TPB   256
#define NB    8
#define R_    16
#define D_    1024

// ---- packed f32x2 helpers ----
__device__ __forceinline__ ull ffma2(ull a, ull b, ull c) {
    ull d;
    asm("fma.rn.f32x2 %0, %1, %2, %3;" : "=l"(d) : "l"(a), "l"(b), "l"(c));
    return d;
}
__device__ __forceinline__ ull fmul2(ull a, ull b) {
    ull d;
    asm("mul.rn.f32x2 %0, %1, %2;" : "=l"(d) : "l"(a), "l"(b));
    return d;
}
__device__ __forceinline__ ull fadd2(ull a, ull b) {
    ull d;
    asm("add.rn.f32x2 %0, %1, %2;" : "=l"(d) : "l"(a), "l"(b));
    return d;
}
__device__ __forceinline__ float lo_(ull v) { return __int_as_float((int)(unsigned)(v & 0xffffffffull)); }
__device__ __forceinline__ float hi_(ull v) { return __int_as_float((int)(unsigned)(v >> 32)); }
__device__ __forceinline__ ull   dup_(float v) {
    ull d;
    asm("mov.b64 %0, {%1, %1};" : "=l"(d) : "r"(__float_as_uint(v)));
    return d;
}
__device__ __forceinline__ ull pack2_(float l, float h) {
    ull d;
    asm("mov.b64 %0, {%1, %2};" : "=l"(d) : "r"(__float_as_uint(l)), "r"(__float_as_uint(h)));
    return d;
}
__device__ __forceinline__ ulonglong2 ldg128(const void* p) {
    ulonglong2 v;
    asm("ld.global.nc.v2.u64 {%0, %1}, [%2];" : "=l"(v.x), "=l"(v.y) : "l"(p));
    return v;
}
__device__ __forceinline__ void stcs128(void* p, ull a, ull b) {
    asm volatile("st.global.cs.v2.u64 [%0], {%1, %2};" :: "l"(p), "l"(a), "l"(b));
}
__device__ __forceinline__ unsigned sptr(const void* p) {
    return (unsigned)__cvta_generic_to_shared(p);
}
__device__ __forceinline__ void cpa16(unsigned dst, const void* src) {
    asm volatile("cp.async.cg.shared.global [%0], [%1], 16;" :: "r"(dst), "l"(src));
}

// ---- dynamic smem layout (per CTA, ~90 KB → 2 CTAs/SM) ----
#define XS_OFF   0                       // ulonglong2 [2][NB][TPB]   65536 B
#define REDP_OFF 65536                   // ull   [NB][TPB]  (x2,xy)  16384 B
#define REDY_OFF 81920                   // float [NB][TPB]  (y2)      8192 B
#define SB_OFF   90112                   // ull   [2][NB][R_]          2048 B
#define SIDX_OFF 92160                   // int   [2][NB]                64 B
#define SCX_OFF  92224                   // ull   [NB]                   64 B
#define SCY_OFF  92288                   // ull   [NB]                   64 B
#define SMEM_TOTAL 92352

__global__ __launch_bounds__(TPB, 2)
void rlora_kernel(const int*   __restrict__ indices,
                  const float* __restrict__ baseW,
                  const float* __restrict__ loraA,
                  const float* __restrict__ loraB,
                  float*       __restrict__ out,
                  int n_rows, int nbatch)
{
    extern __shared__ char smem_raw[];
    ulonglong2 (*xs)[NB][TPB] = reinterpret_cast<ulonglong2(*)[NB][TPB]>(smem_raw + XS_OFF);
    ull   (*redP)[TPB]        = reinterpret_cast<ull(*)[TPB]>(smem_raw + REDP_OFF);
    float (*redY)[TPB]        = reinterpret_cast<float(*)[TPB]>(smem_raw + REDY_OFF);
    ull   (*sb)[NB][R_]       = reinterpret_cast<ull(*)[NB][R_]>(smem_raw + SB_OFF);
    int   (*sidx)[NB]         = reinterpret_cast<int(*)[NB]>(smem_raw + SIDX_OFF);
    ull*  scx                 = reinterpret_cast<ull*>(smem_raw + SCX_OFF);
    ull*  scy                 = reinterpret_cast<ull*>(smem_raw + SCY_OFF);

    const int tid  = threadIdx.x;
    const int wid  = tid >> 5;
    const int lane = tid & 31;
    const int d0   = tid * 4;            // this lane owns columns d0..d0+3

    // lora_A register-resident: a2[r] = A[r][d0..d0+3]  (64 regs)
    ulonglong2 a2[R_];
    #pragma unroll
    for (int r = 0; r < R_; ++r) a2[r] = ldg128(loraA + r * D_ + d0);

    const int S    = gridDim.x;
    const int b0   = blockIdx.x;
    const int kmax = (nbatch - b0 + S - 1) / S;

    // ---------------- prologue ----------------
    #pragma unroll
    for (int row = 0; row < NB; ++row) {
        int g = b0 * NB + row;
        if (g < n_rows) {
            int idx = __ldg(indices + g);
            cpa16(sptr(&xs[0][row][tid]), baseW + (size_t)idx * D_ + d0);
        }
    }
    asm volatile("cp.async.commit_group;");
    if (tid < NB) {
        int g = (b0 + S) * NB + tid;
        sidx[1][tid] = ((b0 + S) < nbatch && g < n_rows) ? __ldg(indices + g) : -1;
    }
    if (tid < NB * R_) {
        int row = tid >> 4, r = tid & 15;
        int g = b0 * NB + row;
        sb[0][row][r] = (g < n_rows)
            ? dup_(0.1f * __ldg(loraB + (size_t)__ldg(indices + g) * R_ + r)) : 0ull;
    }
    __syncthreads();

    for (int k = 0; k < kmax; ++k) {
        const int  buf      = k & 1;
        const bool havenext = (k + 1) < kmax;

        // ---- step 1: cp.async batch k+1 into xs[buf^1] ----
        #pragma unroll
        for (int row = 0; row < NB; ++row) {
            int idx = havenext ? sidx[(k + 1) & 1][row] : -1;
            if (idx >= 0)
                cpa16(sptr(&xs[buf ^ 1][row][tid]), baseW + (size_t)idx * D_ + d0);
        }
        asm volatile("cp.async.commit_group;");

        // ---- step 2: stage sidx(batch k+2) -> slot k&1 ----
        if (tid < NB) {
            long long g = (long long)(b0 + (k + 2) * S) * NB + tid;
            sidx[buf][tid] = ((k + 2) < kmax && g < n_rows) ? __ldg(indices + g) : -1;
        }
        // ---- step 3: stage sb(batch k+1) -> sb[buf^1] ----
        if (tid < NB * R_) {
            int row = tid >> 4, r = tid & 15;
            int idx = havenext ? sidx[(k + 1) & 1][row] : -1;
            sb[buf ^ 1][row][r] = (idx >= 0)
                ? dup_(0.1f * __ldg(loraB + (size_t)idx * R_ + r)) : 0ull;
        }

        // ---- step 4: batch k copies complete (own slices only) ----
        asm volatile("cp.async.wait_group 1;" ::: "memory");

        // ---- step 5: delta + raw partials (shuffle-free) ----
        ulonglong2 xk[NB], dvk[NB];
        #pragma unroll
        for (int row = 0; row < NB; ++row) {
            ulonglong2 xv = xs[buf][row][tid];     // this thread's own copy
            xk[row] = xv;

            const ulonglong2* bp = reinterpret_cast<const ulonglong2*>(sb[buf][row]);
            ulonglong2 b01 = bp[0];
            ull ax0 = fmul2(b01.x, a2[0].x), ay0 = fmul2(b01.x, a2[0].y);
            ull ax1 = fmul2(b01.y, a2[1].x), ay1 = fmul2(b01.y, a2[1].y);
            #pragma unroll
            for (int kk = 1; kk < R_ / 2; ++kk) {
                ulonglong2 b = bp[kk];
                ax0 = ffma2(b.x, a2[2 * kk].x,     ax0);
                ay0 = ffma2(b.x, a2[2 * kk].y,     ay0);
                ax1 = ffma2(b.y, a2[2 * kk + 1].x, ax1);
                ay1 = ffma2(b.y, a2[2 * kk + 1].y, ay1);
            }
            dvk[row].x = fadd2(ax0, ax1);
            dvk[row].y = fadd2(ay0, ay1);

            float x0 = lo_(xv.x), x1 = hi_(xv.x), x2c = lo_(xv.y), x3 = hi_(xv.y);
            float y0 = lo_(dvk[row].x), y1 = hi_(dvk[row].x);
            float y2c = lo_(dvk[row].y), y3 = hi_(dvk[row].y);

            float x2p = fmaf(x0, x0, fmaf(x1, x1, fmaf(x2c, x2c, x3 * x3)));
            float xyp = fmaf(x0, y0, fmaf(x1, y1, fmaf(x2c, y2c, x3 * y3)));
            float y2p = fmaf(y0, y0, fmaf(y1, y1, fmaf(y2c, y2c, y3 * y3)));

            redP[row][tid] = pack2_(x2p, xyp);     // STS.64
            redY[row][tid] = y2p;                  // STS.32
        }
        __syncthreads();

        // ---- step 6: warp w reduces row w (packed trees) + epilogue ----
        {
            const ulonglong2* pP = reinterpret_cast<const ulonglong2*>(redP[wid]);
            ulonglong2 u0 = pP[lane], u1 = pP[lane + 32],
                       u2 = pP[lane + 64], u3 = pP[lane + 96];
            ull sp = fadd2(fadd2(fadd2(u0.x, u0.y), fadd2(u1.x, u1.y)),
                           fadd2(fadd2(u2.x, u2.y), fadd2(u3.x, u3.y)));

            const ulonglong2* pY = reinterpret_cast<const ulonglong2*>(redY[wid]);
            ulonglong2 w0 = pY[lane], w1 = pY[lane + 32];
            ull sy2 = fadd2(fadd2(w0.x, w0.y), fadd2(w1.x, w1.y));

            float a0 = lo_(sp), a1 = hi_(sp);
            float s2 = lo_(sy2) + hi_(sy2);
            #pragma unroll
            for (int off = 16; off > 0; off >>= 1) {
                a0 += __shfl_xor_sync(0xffffffffu, a0, off);
                a1 += __shfl_xor_sync(0xffffffffu, a1, off);
                s2 += __shfl_xor_sync(0xffffffffu, s2, off);
            }
            if (lane == 0) {
                const float MAXN = 1.0f - 1e-5f;
                const float EPSN = 1e-5f;
                float x2 = a0, xy = a1, y2 = s2;

                float nx = sqrtf(x2);
                float sx = (nx > MAXN) ? __fdividef(MAXN, fmaxf(nx, EPSN)) : 1.0f;
                float ny = sqrtf(y2);
                float sy = (ny > MAXN) ? __fdividef(MAXN, fmaxf(ny, EPSN)) : 1.0f;

                float X2 = sx * sx * x2;
                float Y2 = sy * sy * y2;
                float XY = sx * sy * xy;

                float A_  = 1.0f + 2.0f * XY + Y2;
                float B_  = 1.0f - X2;
                float den = fmaxf(1.0f + 2.0f * XY + X2 * Y2, 1e-15f);

                float n2 = (A_ * A_ * X2 + 2.0f * A_ * B_ * XY + B_ * B_ * Y2)
                           / (den * den);
                float no = sqrtf(fmaxf(n2, 0.0f));
                float sf = (no > MAXN) ? __fdividef(MAXN, fmaxf(no, EPSN)) : 1.0f;

                scx[wid] = dup_(__fdividef(sf * A_ * sx, den));
                scy[wid] = dup_(__fdividef(sf * B_ * sy, den));
            }
        }
        __syncthreads();

        // ---- step 7: store batch k (incremental pointer) ----
        const long long row0 = (long long)(b0 + k * S) * NB;
        float* op = out + (size_t)row0 * D_ + d0;
        #pragma unroll
        for (int row = 0; row < NB; ++row) {
            if (row0 + row < n_rows) {
                ull o0 = ffma2(scx[row], xk[row].x, fmul2(scy[row], dvk[row].x));
                ull o1 = ffma2(scx[row], xk[row].y, fmul2(scy[row], dvk[row].y));
                stcs128(op, o0, o1);
            }
            op += D_;
        }
    }
}

extern "C" void kernel_launch(void* const* d_in, const int* in_sizes, int n_in,
                              void* d_out, int out_size)
{
    const int*   indices = (const int*)  d_in[0];
    const float* baseW   = (const float*)d_in[1];
    const float* loraA   = (const float*)d_in[2];
    const float* loraB   = (const float*)d_in[3];
    float*       out     = (float*)d_out;

    int n_rows = in_sizes[0];                    // 32768
    int nbatch = (n_rows + NB - 1) / NB;         // 4096
    int grid   = nbatch < 2 * 148 ? nbatch : 2 * 148;   // 2 CTAs/SM

    cudaFuncSetAttribute(rlora_kernel,
                         cudaFuncAttributeMaxDynamicSharedMemorySize, SMEM_TOTAL);
    rlora_kernel<<<grid, TPB, SMEM_TOTAL>>>(indices, baseW, loraA, loraB, out,
                                            n_rows, nbatch);
}

// round 16
// speedup vs baseline: 1.1773x; 1.0559x over previous
#include <cuda_runtime.h>
#include <cstdint>

typedef unsigned long long ull;

#define TPB   256
#define NB    8
#define R_    16
#define D_    1024

// ---- packed f32x2 helpers ----
__device__ __forceinline__ ull ffma2(ull a, ull b, ull c) {
    ull d;
    asm("fma.rn.f32x2 %0, %1, %2, %3;" : "=l"(d) : "l"(a), "l"(b), "l"(c));
    return d;
}
__device__ __forceinline__ ull fmul2(ull a, ull b) {
    ull d;
    asm("mul.rn.f32x2 %0, %1, %2;" : "=l"(d) : "l"(a), "l"(b));
    return d;
}
__device__ __forceinline__ ull fadd2(ull a, ull b) {
    ull d;
    asm("add.rn.f32x2 %0, %1, %2;" : "=l"(d) : "l"(a), "l"(b));
    return d;
}
__device__ __forceinline__ float lo_(ull v) { return __int_as_float((int)(unsigned)(v & 0xffffffffull)); }
__device__ __forceinline__ float hi_(ull v) { return __int_as_float((int)(unsigned)(v >> 32)); }
__device__ __forceinline__ ull   dup_(float v) {
    ull d;
    asm("mov.b64 %0, {%1, %1};" : "=l"(d) : "r"(__float_as_uint(v)));
    return d;
}
__device__ __forceinline__ ull pack2_(float l, float h) {
    ull d;
    asm("mov.b64 %0, {%1, %2};" : "=l"(d) : "r"(__float_as_uint(l)), "r"(__float_as_uint(h)));
    return d;
}
__device__ __forceinline__ ulonglong2 ldg128(const void* p) {
    ulonglong2 v;
    asm("ld.global.nc.v2.u64 {%0, %1}, [%2];" : "=l"(v.x), "=l"(v.y) : "l"(p));
    return v;
}
__device__ __forceinline__ void stcs128(void* p, ull a, ull b) {
    asm volatile("st.global.cs.v2.u64 [%0], {%1, %2};" :: "l"(p), "l"(a), "l"(b));
}
__device__ __forceinline__ unsigned sptr(const void* p) {
    return (unsigned)__cvta_generic_to_shared(p);
}
__device__ __forceinline__ void cpa16(unsigned dst, const void* src) {
    asm volatile("cp.async.cg.shared.global [%0], [%1], 16;" :: "r"(dst), "l"(src));
}

// ---- dynamic smem layout (per CTA, ~90 KB → 2 CTAs/SM) ----
#define XS_OFF   0                       // ulonglong2 [2][NB][TPB]   65536 B
#define REDP_OFF 65536                   // ull   [NB][TPB]  (x2,xy)  16384 B
#define REDY_OFF 81920                   // float [NB][TPB]  (y2)      8192 B
#define SB_OFF   90112                   // ull   [2][NB][R_]          2048 B
#define SIDX_OFF 92160                   // int   [2][NB]                64 B
#define SCX_OFF  92224                   // ull   [NB]                   64 B
#define SCY_OFF  92288                   // ull   [NB]                   64 B
#define SMEM_TOTAL 92352

__global__ __launch_bounds__(TPB, 2)
void rlora_kernel(const int*   __restrict__ indices,
                  const float* __restrict__ baseW,
                  const float* __restrict__ loraA,
                  const float* __restrict__ loraB,
                  float*       __restrict__ out,
                  int n_rows, int nbatch)
{
    extern __shared__ char smem_raw[];
    ulonglong2 (*xs)[NB][TPB] = reinterpret_cast<ulonglong2(*)[NB][TPB]>(smem_raw + XS_OFF);
    ull   (*redP)[TPB]        = reinterpret_cast<ull(*)[TPB]>(smem_raw + REDP_OFF);
    float (*redY)[TPB]        = reinterpret_cast<float(*)[TPB]>(smem_raw + REDY_OFF);
    ull   (*sb)[NB][R_]       = reinterpret_cast<ull(*)[NB][R_]>(smem_raw + SB_OFF);
    int   (*sidx)[NB]         = reinterpret_cast<int(*)[NB]>(smem_raw + SIDX_OFF);
    ull*  scx                 = reinterpret_cast<ull*>(smem_raw + SCX_OFF);
    ull*  scy                 = reinterpret_cast<ull*>(smem_raw + SCY_OFF);

    const int tid  = threadIdx.x;
    const int wid  = tid >> 5;
    const int lane = tid & 31;
    const int d0   = tid * 4;            // this lane owns columns d0..d0+3

    // lora_A register-resident: a2[r] = A[r][d0..d0+3]  (64 regs)
    ulonglong2 a2[R_];
    #pragma unroll
    for (int r = 0; r < R_; ++r) a2[r] = ldg128(loraA + r * D_ + d0);

    const int S    = gridDim.x;
    const int b0   = blockIdx.x;
    const int kmax = (nbatch - b0 + S - 1) / S;

    // ---------------- prologue ----------------
    #pragma unroll
    for (int row = 0; row < NB; ++row) {
        int g = b0 * NB + row;
        if (g < n_rows) {
            int idx = __ldg(indices + g);
            cpa16(sptr(&xs[0][row][tid]), baseW + (size_t)idx * D_ + d0);
        }
    }
    asm volatile("cp.async.commit_group;");
    if (tid < NB) {
        int g = (b0 + S) * NB + tid;
        sidx[1][tid] = ((b0 + S) < nbatch && g < n_rows) ? __ldg(indices + g) : -1;
    }
    if (tid < NB * R_) {
        int row = tid >> 4, r = tid & 15;
        int g = b0 * NB + row;
        sb[0][row][r] = (g < n_rows)
            ? dup_(0.1f * __ldg(loraB + (size_t)__ldg(indices + g) * R_ + r)) : 0ull;
    }
    __syncthreads();

    for (int k = 0; k < kmax; ++k) {
        const int  buf      = k & 1;
        const bool havenext = (k + 1) < kmax;

        // ---- step 1: cp.async batch k+1 into xs[buf^1] ----
        #pragma unroll
        for (int row = 0; row < NB; ++row) {
            int idx = havenext ? sidx[(k + 1) & 1][row] : -1;
            if (idx >= 0)
                cpa16(sptr(&xs[buf ^ 1][row][tid]), baseW + (size_t)idx * D_ + d0);
        }
        asm volatile("cp.async.commit_group;");

        // ---- step 2: stage sidx(batch k+2) -> slot k&1 ----
        if (tid < NB) {
            long long g = (long long)(b0 + (k + 2) * S) * NB + tid;
            sidx[buf][tid] = ((k + 2) < kmax && g < n_rows) ? __ldg(indices + g) : -1;
        }
        // ---- step 3: stage sb(batch k+1) -> sb[buf^1] ----
        if (tid < NB * R_) {
            int row = tid >> 4, r = tid & 15;
            int idx = havenext ? sidx[(k + 1) & 1][row] : -1;
            sb[buf ^ 1][row][r] = (idx >= 0)
                ? dup_(0.1f * __ldg(loraB + (size_t)idx * R_ + r)) : 0ull;
        }

        // ---- step 4: batch k copies complete (own slices only) ----
        asm volatile("cp.async.wait_group 1;" ::: "memory");

        // ---- step 5: delta + raw partials (shuffle-free); x NOT kept live ----
        ulonglong2 dvk[NB];
        #pragma unroll
        for (int row = 0; row < NB; ++row) {
            ulonglong2 xv = xs[buf][row][tid];     // this thread's own copy

            const ulonglong2* bp = reinterpret_cast<const ulonglong2*>(sb[buf][row]);
            ulonglong2 b01 = bp[0];
            ull ax0 = fmul2(b01.x, a2[0].x), ay0 = fmul2(b01.x, a2[0].y);
            ull ax1 = fmul2(b01.y, a2[1].x), ay1 = fmul2(b01.y, a2[1].y);
            #pragma unroll
            for (int kk = 1; kk < R_ / 2; ++kk) {
                ulonglong2 b = bp[kk];
                ax0 = ffma2(b.x, a2[2 * kk].x,     ax0);
                ay0 = ffma2(b.x, a2[2 * kk].y,     ay0);
                ax1 = ffma2(b.y, a2[2 * kk + 1].x, ax1);
                ay1 = ffma2(b.y, a2[2 * kk + 1].y, ay1);
            }
            dvk[row].x = fadd2(ax0, ax1);
            dvk[row].y = fadd2(ay0, ay1);

            float x0 = lo_(xv.x), x1 = hi_(xv.x), x2c = lo_(xv.y), x3 = hi_(xv.y);
            float y0 = lo_(dvk[row].x), y1 = hi_(dvk[row].x);
            float y2c = lo_(dvk[row].y), y3 = hi_(dvk[row].y);

            float x2p = fmaf(x0, x0, fmaf(x1, x1, fmaf(x2c, x2c, x3 * x3)));
            float xyp = fmaf(x0, y0, fmaf(x1, y1, fmaf(x2c, y2c, x3 * y3)));
            float y2p = fmaf(y0, y0, fmaf(y1, y1, fmaf(y2c, y2c, y3 * y3)));

            redP[row][tid] = pack2_(x2p, xyp);     // STS.64
            redY[row][tid] = y2p;                  // STS.32
        }
        __syncthreads();

        // ---- step 6: warp w reduces row w (packed trees) + epilogue ----
        {
            const ulonglong2* pP = reinterpret_cast<const ulonglong2*>(redP[wid]);
            ulonglong2 u0 = pP[lane], u1 = pP[lane + 32],
                       u2 = pP[lane + 64], u3 = pP[lane + 96];
            ull sp = fadd2(fadd2(fadd2(u0.x, u0.y), fadd2(u1.x, u1.y)),
                           fadd2(fadd2(u2.x, u2.y), fadd2(u3.x, u3.y)));

            const ulonglong2* pY = reinterpret_cast<const ulonglong2*>(redY[wid]);
            ulonglong2 w0 = pY[lane], w1 = pY[lane + 32];
            ull sy2 = fadd2(fadd2(w0.x, w0.y), fadd2(w1.x, w1.y));

            float a0 = lo_(sp), a1 = hi_(sp);
            float s2 = lo_(sy2) + hi_(sy2);
            #pragma unroll
            for (int off = 16; off > 0; off >>= 1) {
                a0 += __shfl_xor_sync(0xffffffffu, a0, off);
                a1 += __shfl_xor_sync(0xffffffffu, a1, off);
                s2 += __shfl_xor_sync(0xffffffffu, s2, off);
            }
            if (lane == 0) {
                const float MAXN = 1.0f - 1e-5f;
                const float EPSN = 1e-5f;
                float x2 = a0, xy = a1, y2 = s2;

                float nx = sqrtf(x2);
                float sx = (nx > MAXN) ? __fdividef(MAXN, fmaxf(nx, EPSN)) : 1.0f;
                float ny = sqrtf(y2);
                float sy = (ny > MAXN) ? __fdividef(MAXN, fmaxf(ny, EPSN)) : 1.0f;

                float X2 = sx * sx * x2;
                float Y2 = sy * sy * y2;
                float XY = sx * sy * xy;

                float A_  = 1.0f + 2.0f * XY + Y2;
                float B_  = 1.0f - X2;
                float den = fmaxf(1.0f + 2.0f * XY + X2 * Y2, 1e-15f);

                float n2 = (A_ * A_ * X2 + 2.0f * A_ * B_ * XY + B_ * B_ * Y2)
                           / (den * den);
                float no = sqrtf(fmaxf(n2, 0.0f));
                float sf = (no > MAXN) ? __fdividef(MAXN, fmaxf(no, EPSN)) : 1.0f;

                scx[wid] = dup_(__fdividef(sf * A_ * sx, den));
                scy[wid] = dup_(__fdividef(sf * B_ * sy, den));
            }
        }
        __syncthreads();

        // ---- step 7: store batch k (x re-read from smem; slot not yet recycled) ----
        const long long row0 = (long long)(b0 + k * S) * NB;
        float* op = out + (size_t)row0 * D_ + d0;
        #pragma unroll
        for (int row = 0; row < NB; ++row) {
            if (row0 + row < n_rows) {
                ulonglong2 xv = xs[buf][row][tid];
                ull o0 = ffma2(scx[row], xv.x, fmul2(scy[row], dvk[row].x));
                ull o1 = ffma2(scx[row], xv.y, fmul2(scy[row], dvk[row].y));
                stcs128(op, o0, o1);
            }
            op += D_;
        }
    }
}

extern "C" void kernel_launch(void* const* d_in, const int* in_sizes, int n_in,
                              void* d_out, int out_size)
{
    const int*   indices = (const int*)  d_in[0];
    const float* baseW   = (const float*)d_in[1];
    const float* loraA   = (const float*)d_in[2];
    const float* loraB   = (const float*)d_in[3];
    float*       out     = (float*)d_out;

    int n_rows = in_sizes[0];                    // 32768
    int nbatch = (n_rows + NB - 1) / NB;         // 4096
    int grid   = nbatch < 2 * 148 ? nbatch : 2 * 148;   // 2 CTAs/SM

    cudaFuncSetAttribute(rlora_kernel,
                         cudaFuncAttributeMaxDynamicSharedMemorySize, SMEM_TOTAL);
    rlora_kernel<<<grid, TPB, SMEM_TOTAL>>>(indices, baseW, loraA, loraB, out,
                                            n_rows, nbatch);
}